// round 11
// baseline (speedup 1.0000x reference)
#include <cuda_runtime.h>
#include <math.h>

#define BATCH 2
#define SEQ   2000
#define DM    256
#define DI    512
#define DS    16
#define DTR   16
#define NXP   (DTR + 2*DS)   /* 48 */
#define NT    (BATCH*SEQ)    /* 4000 */
#define NL    4
#define NCHUNK 16
#define CLEN  (SEQ / NCHUNK)  /* 125 */

// ---------------- scratch (static device globals; no allocation) ----------------
static __device__ float g_h   [NT*DM];        // residual stream
static __device__ float g_hn  [NT*DM];        // layernormed h
static __device__ float g_xz  [NT*2*DI];      // in_proj output (u | z)
static __device__ float g_u   [NT*DI];        // post-conv + silu
static __device__ float g_xdbc[NT*NXP];       // x_proj output (dt_r | B | C)
static __device__ float g_dt  [NT*DI];        // softplus(dt)
static __device__ float g_y   [NT*DI];        // scan output (gated)
// chunked-scan carries: [chunk][b][d][n]
static __device__ float g_aprod[NCHUNK*BATCH*DI*DS];
static __device__ float g_send [NCHUNK*BATCH*DI*DS];
static __device__ float g_cin  [NCHUNK*BATCH*DI*DS];

// ---------------- helpers ----------------
__device__ __forceinline__ float blockReduceSum256(float v) {
    __shared__ float sh[8];
    __shared__ float total;
    #pragma unroll
    for (int o = 16; o > 0; o >>= 1) v += __shfl_xor_sync(0xffffffffu, v, o);
    if ((threadIdx.x & 31) == 0) sh[threadIdx.x >> 5] = v;
    __syncthreads();
    if (threadIdx.x == 0) {
        float s = 0.f;
        #pragma unroll
        for (int i = 0; i < 8; i++) s += sh[i];
        total = s;
    }
    __syncthreads();
    return total;
}

// ---------------- kernels ----------------

// h = x[...,None]*w + b + gene_emb + mod_emb
__global__ void embed_kernel(const float* __restrict__ x,
                             const float* __restrict__ w,
                             const float* __restrict__ b,
                             const float* __restrict__ ge,
                             const float* __restrict__ me) {
    int i = blockIdx.x * 256 + threadIdx.x;
    if (i >= NT * DM) return;
    int d = i & (DM - 1);
    int t = i >> 8;
    int l = t % SEQ;
    g_h[i] = x[t] * w[d] + b[d] + ge[l * DM + d] + me[d];
}

// LayerNorm over last dim (256); one block per token
__global__ void ln_kernel(const float* __restrict__ in, float* __restrict__ out,
                          const float* __restrict__ w, const float* __restrict__ b) {
    int t = blockIdx.x, d = threadIdx.x;
    float v = in[t * DM + d];
    float mean = blockReduceSum256(v) * (1.f / DM);
    float diff = v - mean;
    float var = blockReduceSum256(diff * diff) * (1.f / DM);
    out[t * DM + d] = diff * rsqrtf(var + 1e-5f) * w[d] + b[d];
}

// ---------------- high-throughput SGEMM ----------------
// C[M,N] = A[M,K] @ W[N,K]^T, optional accumulate.
// BM=128, BN in {128,64}, BK=16, 256 threads, micro-tile 8 x (BN/16).
// Register-prefetch of next k-tile overlaps gmem latency with compute.
template<int BN, int ACCUM>
__global__ void __launch_bounds__(256, 2)
sgemm_big(const float* __restrict__ A, const float* __restrict__ W,
          float* __restrict__ C, int M, int N, int K) {
    constexpr int BM = 128, BK = 16;
    constexpr int TN = BN / 16;          // 8 or 4 cols per thread
    constexpr int NWL = BN / 64;         // W float4 loads per thread (2 or 1)
    __shared__ float As[BK][BM + 4];
    __shared__ float Ws[BK][BN + 4];

    const int tid = threadIdx.x;
    const int m0 = blockIdx.y * BM, n0 = blockIdx.x * BN;
    const int tx = tid & 15, ty = tid >> 4;

    // loader mapping: float4 granules, (row, c4) with c4 = k-group
    const int lr = tid >> 2;             // 0..63
    const int lc = tid & 3;              // 0..3  (k offset = lc*4)

    float acc[8][TN];
    #pragma unroll
    for (int i = 0; i < 8; i++)
        #pragma unroll
        for (int j = 0; j < TN; j++) acc[i][j] = 0.f;

    const float4 f4z = make_float4(0.f, 0.f, 0.f, 0.f);
    float4 pa0, pa1, pw[NWL];

    // prefetch tile 0
    {
        int r0 = m0 + lr, r1 = m0 + lr + 64;
        pa0 = (r0 < M) ? *reinterpret_cast<const float4*>(A + (size_t)r0 * K + lc * 4) : f4z;
        pa1 = (r1 < M) ? *reinterpret_cast<const float4*>(A + (size_t)r1 * K + lc * 4) : f4z;
        #pragma unroll
        for (int q = 0; q < NWL; q++)
            pw[q] = *reinterpret_cast<const float4*>(W + (size_t)(n0 + lr + 64 * q) * K + lc * 4);
    }

    for (int kt = 0; kt < K; kt += BK) {
        // stage prefetched tile into smem (transposed)
        As[lc * 4 + 0][lr]      = pa0.x;
        As[lc * 4 + 1][lr]      = pa0.y;
        As[lc * 4 + 2][lr]      = pa0.z;
        As[lc * 4 + 3][lr]      = pa0.w;
        As[lc * 4 + 0][lr + 64] = pa1.x;
        As[lc * 4 + 1][lr + 64] = pa1.y;
        As[lc * 4 + 2][lr + 64] = pa1.z;
        As[lc * 4 + 3][lr + 64] = pa1.w;
        #pragma unroll
        for (int q = 0; q < NWL; q++) {
            Ws[lc * 4 + 0][lr + 64 * q] = pw[q].x;
            Ws[lc * 4 + 1][lr + 64 * q] = pw[q].y;
            Ws[lc * 4 + 2][lr + 64 * q] = pw[q].z;
            Ws[lc * 4 + 3][lr + 64 * q] = pw[q].w;
        }
        __syncthreads();

        // prefetch next tile (LDGs in flight during compute)
        if (kt + BK < K) {
            int kn = kt + BK;
            int r0 = m0 + lr, r1 = m0 + lr + 64;
            pa0 = (r0 < M) ? *reinterpret_cast<const float4*>(A + (size_t)r0 * K + kn + lc * 4) : f4z;
            pa1 = (r1 < M) ? *reinterpret_cast<const float4*>(A + (size_t)r1 * K + kn + lc * 4) : f4z;
            #pragma unroll
            for (int q = 0; q < NWL; q++)
                pw[q] = *reinterpret_cast<const float4*>(W + (size_t)(n0 + lr + 64 * q) * K + kn + lc * 4);
        }

        #pragma unroll
        for (int kk = 0; kk < BK; kk++) {
            float a[8], w[TN];
            float4 av0 = *reinterpret_cast<const float4*>(&As[kk][ty * 8]);
            float4 av1 = *reinterpret_cast<const float4*>(&As[kk][ty * 8 + 4]);
            a[0] = av0.x; a[1] = av0.y; a[2] = av0.z; a[3] = av0.w;
            a[4] = av1.x; a[5] = av1.y; a[6] = av1.z; a[7] = av1.w;
            #pragma unroll
            for (int j4 = 0; j4 < TN; j4 += 4) {
                float4 wv = *reinterpret_cast<const float4*>(&Ws[kk][tx * TN + j4]);
                w[j4 + 0] = wv.x; w[j4 + 1] = wv.y; w[j4 + 2] = wv.z; w[j4 + 3] = wv.w;
            }
            #pragma unroll
            for (int i = 0; i < 8; i++)
                #pragma unroll
                for (int j = 0; j < TN; j++)
                    acc[i][j] = fmaf(a[i], w[j], acc[i][j]);
        }
        __syncthreads();
    }

    // writeback (float4, guarded on M)
    #pragma unroll
    for (int i = 0; i < 8; i++) {
        int m = m0 + ty * 8 + i;
        if (m >= M) continue;
        float* cr = C + (size_t)m * N + n0 + tx * TN;
        #pragma unroll
        for (int j4 = 0; j4 < TN; j4 += 4) {
            float4 v = make_float4(acc[i][j4], acc[i][j4 + 1], acc[i][j4 + 2], acc[i][j4 + 3]);
            if (ACCUM) {
                float4 o = *reinterpret_cast<const float4*>(cr + j4);
                v.x += o.x; v.y += o.y; v.z += o.z; v.w += o.w;
            }
            *reinterpret_cast<float4*>(cr + j4) = v;
        }
    }
}

// Depthwise causal conv (D_CONV=4) over u-half of xz, + bias, + SiLU
__global__ void conv_silu_kernel(const float* __restrict__ cw,
                                 const float* __restrict__ cb) {
    int idx = blockIdx.x * 256 + threadIdx.x;
    if (idx >= NT * DI) return;
    int d = idx & (DI - 1);
    int t = idx >> 9;
    int l = t % SEQ;
    float s = cb[d];
    #pragma unroll
    for (int k = 0; k < 4; k++) {
        int ls = l + k - 3;
        if (ls >= 0) s = fmaf(g_xz[(size_t)(t - l + ls) * (2 * DI) + d], cw[d * 4 + k], s);
    }
    g_u[idx] = s / (1.f + __expf(-s));
}

// xdbc[t, n<48] = sum_k u[t,k] * xpw[n,k]
__global__ void xproj_kernel(const float* __restrict__ xpw) {
    int idx = blockIdx.x * 256 + threadIdx.x;
    if (idx >= NT * NXP) return;
    int n = idx % NXP;
    int t = idx / NXP;
    const float4* ur = reinterpret_cast<const float4*>(g_u + (size_t)t * DI);
    const float4* wr = reinterpret_cast<const float4*>(xpw + (size_t)n * DI);
    float s = 0.f;
    #pragma unroll 4
    for (int k = 0; k < DI / 4; k++) {
        float4 a = ur[k], w = wr[k];
        s += a.x * w.x + a.y * w.y + a.z * w.z + a.w * w.w;
    }
    g_xdbc[idx] = s;
}

// dt[t,d] = softplus( xdbc[t,:16] . dtw[d,:] + dtb[d] )
__global__ void dt_kernel(const float* __restrict__ dtw,
                          const float* __restrict__ dtb) {
    int idx = blockIdx.x * 256 + threadIdx.x;
    if (idx >= NT * DI) return;
    int d = idx & (DI - 1);
    int t = idx >> 9;
    const float* r = g_xdbc + (size_t)t * NXP;
    const float* w = dtw + (size_t)d * DTR;
    float s = dtb[d];
    #pragma unroll
    for (int k = 0; k < DTR; k++) s = fmaf(r[k], w[k], s);
    g_dt[idx] = (s > 20.f) ? s : log1pf(__expf(s));
}

// ---- chunked selective scan ----
// Pass 1: per chunk compute (prod dA, local scan end) with zero initial state.
__global__ void scan_pass1(const float* __restrict__ A_log) {
    int gid = blockIdx.x * 256 + threadIdx.x;   // 262144 threads
    int n = gid & 15;
    int r = gid >> 4;
    int d = r & (DI - 1);
    int b = (r >> 9) & (BATCH - 1);
    int c = r >> 10;
    const float Ac = -__expf(A_log[d * DS + n]);
    float state = 0.f, aprod = 1.f;
    const int t0 = b * SEQ + c * CLEN;
    #pragma unroll 5
    for (int l = 0; l < CLEN; l++) {
        int t = t0 + l;
        float dtv = g_dt[(size_t)t * DI + d];
        float uv  = g_u [(size_t)t * DI + d];
        float Bv  = g_xdbc[(size_t)t * NXP + DTR + n];
        float dA = __expf(dtv * Ac);
        aprod *= dA;
        state = fmaf(dA, state, dtv * Bv * uv);
    }
    int idx = ((c * BATCH + b) * DI + d) * DS + n;
    g_aprod[idx] = aprod;
    g_send[idx]  = state;
}

// Pass 2: serial prefix over the 16 chunks per (b,d,n) -> carry-in per chunk.
__global__ void scan_carry() {
    int gid = blockIdx.x * 256 + threadIdx.x;   // 16384 threads
    int n = gid & 15;
    int d = (gid >> 4) & (DI - 1);
    int b = gid >> 13;
    float carry = 0.f;
    #pragma unroll
    for (int c = 0; c < NCHUNK; c++) {
        int idx = ((c * BATCH + b) * DI + d) * DS + n;
        g_cin[idx] = carry;
        carry = fmaf(g_aprod[idx], carry, g_send[idx]);
    }
}

// Pass 3: rescan each chunk from its carry-in, emit gated output.
__global__ void scan_pass2(const float* __restrict__ A_log,
                           const float* __restrict__ Dv) {
    int gid = blockIdx.x * 256 + threadIdx.x;   // 262144 threads
    int n = gid & 15;
    int r = gid >> 4;
    int d = r & (DI - 1);
    int b = (r >> 9) & (BATCH - 1);
    int c = r >> 10;
    const float Ac = -__expf(A_log[d * DS + n]);
    const float Dd = Dv[d];
    float state = g_cin[((c * BATCH + b) * DI + d) * DS + n];
    const int t0 = b * SEQ + c * CLEN;
    #pragma unroll 5
    for (int l = 0; l < CLEN; l++) {
        int t = t0 + l;
        float dtv = g_dt[(size_t)t * DI + d];
        float uv  = g_u [(size_t)t * DI + d];
        float Bv  = g_xdbc[(size_t)t * NXP + DTR + n];
        float Cv  = g_xdbc[(size_t)t * NXP + DTR + DS + n];
        float dA = __expf(dtv * Ac);
        state = fmaf(dA, state, dtv * Bv * uv);
        float p = state * Cv;
        p += __shfl_xor_sync(0xffffffffu, p, 1, 16);
        p += __shfl_xor_sync(0xffffffffu, p, 2, 16);
        p += __shfl_xor_sync(0xffffffffu, p, 4, 16);
        p += __shfl_xor_sync(0xffffffffu, p, 8, 16);
        if (n == 0) {
            float z = g_xz[(size_t)t * (2 * DI) + DI + d];
            g_y[(size_t)t * DI + d] = (p + uv * Dd) * (z / (1.f + __expf(-z)));
        }
    }
}

// Final LN + head dot product; one block per token
__global__ void final_kernel(const float* __restrict__ fw, const float* __restrict__ fb,
                             const float* __restrict__ hw, const float* __restrict__ hb,
                             float* __restrict__ out) {
    int t = blockIdx.x, d = threadIdx.x;
    float v = g_h[t * DM + d];
    float mean = blockReduceSum256(v) * (1.f / DM);
    float diff = v - mean;
    float var = blockReduceSum256(diff * diff) * (1.f / DM);
    float nr = diff * rsqrtf(var + 1e-5f) * fw[d] + fb[d];
    float s = blockReduceSum256(nr * hw[d]);
    if (d == 0) out[t] = s + hb[0];
}

// ---------------- launch ----------------
extern "C" void kernel_launch(void* const* d_in, const int* in_sizes, int n_in,
                              void* d_out, int out_size) {
    const float* x         = (const float*)d_in[0];
    const float* bulk_in_w = (const float*)d_in[1];
    const float* bulk_in_b = (const float*)d_in[2];
    const float* gene_emb  = (const float*)d_in[3];
    const float* mod_emb   = (const float*)d_in[4];
    const float* ln_w      = (const float*)d_in[5];
    const float* ln_b      = (const float*)d_in[6];
    const float* in_proj_w = (const float*)d_in[7];
    const float* conv_w    = (const float*)d_in[8];
    const float* conv_b    = (const float*)d_in[9];
    const float* x_proj_w  = (const float*)d_in[10];
    const float* dt_proj_w = (const float*)d_in[11];
    const float* dt_proj_b = (const float*)d_in[12];
    const float* A_log     = (const float*)d_in[13];
    const float* Dvec      = (const float*)d_in[14];
    const float* out_proj_w= (const float*)d_in[15];
    const float* fin_w     = (const float*)d_in[16];
    const float* fin_b     = (const float*)d_in[17];
    const float* head_w    = (const float*)d_in[18];
    const float* head_b    = (const float*)d_in[19];
    float* out = (float*)d_out;

    float *p_h, *p_hn, *p_xz, *p_y;
    cudaGetSymbolAddress((void**)&p_h,  g_h);
    cudaGetSymbolAddress((void**)&p_hn, g_hn);
    cudaGetSymbolAddress((void**)&p_xz, g_xz);
    cudaGetSymbolAddress((void**)&p_y,  g_y);

    embed_kernel<<<(NT * DM + 255) / 256, 256>>>(x, bulk_in_w, bulk_in_b, gene_emb, mod_emb);

    for (int i = 0; i < NL; i++) {
        ln_kernel<<<NT, 256>>>(p_h, p_hn, ln_w + i * DM, ln_b + i * DM);

        // xz = hn @ in_proj_w^T   (M=4000, N=1024, K=256)  [128x128 tiles]
        sgemm_big<128, 0><<<dim3((2 * DI) / 128, (NT + 127) / 128), 256>>>(
            p_hn, in_proj_w + (size_t)i * (2 * DI) * DM, p_xz, NT, 2 * DI, DM);

        conv_silu_kernel<<<(NT * DI + 255) / 256, 256>>>(conv_w + (size_t)i * DI * 4,
                                                         conv_b + (size_t)i * DI);

        xproj_kernel<<<(NT * NXP + 255) / 256, 256>>>(x_proj_w + (size_t)i * NXP * DI);

        dt_kernel<<<(NT * DI + 255) / 256, 256>>>(dt_proj_w + (size_t)i * DI * DTR,
                                                  dt_proj_b + (size_t)i * DI);

        scan_pass1<<<(BATCH * DI * DS * NCHUNK) / 256, 256>>>(A_log + (size_t)i * DI * DS);
        scan_carry<<<(BATCH * DI * DS) / 256, 256>>>();
        scan_pass2<<<(BATCH * DI * DS * NCHUNK) / 256, 256>>>(A_log + (size_t)i * DI * DS,
                                                              Dvec + (size_t)i * DI);

        // h += y @ out_proj_w^T   (M=4000, N=256, K=512)  [128x64 tiles]
        sgemm_big<64, 1><<<dim3(DM / 64, (NT + 127) / 128), 256>>>(
            p_y, out_proj_w + (size_t)i * DM * DI, p_h, NT, DM, DI);
    }

    final_kernel<<<NT, 256>>>(fin_w, fin_b, head_w, head_b, out);
}

// round 14
// speedup vs baseline: 1.3032x; 1.3032x over previous
#include <cuda_runtime.h>
#include <math.h>

#define BATCH 2
#define SEQ   2000
#define DM    256
#define DI    512
#define DS    16
#define DTR   16
#define NXP   (DTR + 2*DS)   /* 48 */
#define NT    (BATCH*SEQ)    /* 4000 */
#define NL    4
#define NCHUNK 16
#define CLEN  (SEQ / NCHUNK)  /* 125 */

// ---------------- scratch (static device globals; no allocation) ----------------
static __device__ float g_h   [NT*DM];        // residual stream
static __device__ float g_hn  [NT*DM];        // layernormed h
static __device__ float g_xz  [NT*2*DI];      // in_proj output (u | z)
static __device__ float g_u   [NT*DI];        // post-conv + silu
static __device__ float g_xdbc[NT*NXP];       // x_proj output (dt_r | B | C)
static __device__ float g_dt  [NT*DI];        // softplus(dt)
static __device__ float g_y   [NT*DI];        // scan output (gated)
// chunked-scan carries: [chunk][b][d][n]
static __device__ float g_aprod[NCHUNK*BATCH*DI*DS];
static __device__ float g_send [NCHUNK*BATCH*DI*DS];

// ---------------- helpers ----------------
__device__ __forceinline__ float blockReduceSum256(float v) {
    __shared__ float sh[8];
    __shared__ float total;
    #pragma unroll
    for (int o = 16; o > 0; o >>= 1) v += __shfl_xor_sync(0xffffffffu, v, o);
    if ((threadIdx.x & 31) == 0) sh[threadIdx.x >> 5] = v;
    __syncthreads();
    if (threadIdx.x == 0) {
        float s = 0.f;
        #pragma unroll
        for (int i = 0; i < 8; i++) s += sh[i];
        total = s;
    }
    __syncthreads();
    return total;
}

// ---------------- kernels ----------------

// h = x[...,None]*w + b + gene_emb + mod_emb
__global__ void embed_kernel(const float* __restrict__ x,
                             const float* __restrict__ w,
                             const float* __restrict__ b,
                             const float* __restrict__ ge,
                             const float* __restrict__ me) {
    int i = blockIdx.x * 256 + threadIdx.x;
    if (i >= NT * DM) return;
    int d = i & (DM - 1);
    int t = i >> 8;
    int l = t % SEQ;
    g_h[i] = x[t] * w[d] + b[d] + ge[l * DM + d] + me[d];
}

// LayerNorm over last dim (256); one block per token
__global__ void ln_kernel(const float* __restrict__ in, float* __restrict__ out,
                          const float* __restrict__ w, const float* __restrict__ b) {
    int t = blockIdx.x, d = threadIdx.x;
    float v = in[t * DM + d];
    float mean = blockReduceSum256(v) * (1.f / DM);
    float diff = v - mean;
    float var = blockReduceSum256(diff * diff) * (1.f / DM);
    out[t * DM + d] = diff * rsqrtf(var + 1e-5f) * w[d] + b[d];
}

// ---------------- SGEMM (spill-safe tiles) ----------------
// C[M,N] = A[M,K] @ W[N,K]^T, optional accumulate.
// 256 threads; micro-tile (BM/16)x(BN/16); register prefetch of next k-tile.
template<int BM, int BN, int ACCUM>
__global__ void __launch_bounds__(256)
sgemm_nt2(const float* __restrict__ A, const float* __restrict__ W,
          float* __restrict__ C, int M, int N, int K) {
    constexpr int BK = 16;
    constexpr int TM = BM / 16, TN = BN / 16;
    constexpr int NAL = BM / 64, NWL = BN / 64;
    __shared__ float As[BK][BM + 4];
    __shared__ float Ws[BK][BN + 4];

    const int tid = threadIdx.x;
    const int m0 = blockIdx.y * BM, n0 = blockIdx.x * BN;
    const int tx = tid & 15, ty = tid >> 4;
    const int lr = tid >> 2;             // 0..63
    const int lc = tid & 3;              // k-group (offset lc*4)

    float acc[TM][TN];
    #pragma unroll
    for (int i = 0; i < TM; i++)
        #pragma unroll
        for (int j = 0; j < TN; j++) acc[i][j] = 0.f;

    const float4 f4z = make_float4(0.f, 0.f, 0.f, 0.f);
    float4 pa[NAL], pw[NWL];

    // prefetch k-tile 0
    #pragma unroll
    for (int q = 0; q < NAL; q++) {
        int r = m0 + lr + 64 * q;
        pa[q] = (r < M) ? *reinterpret_cast<const float4*>(A + (size_t)r * K + lc * 4) : f4z;
    }
    #pragma unroll
    for (int q = 0; q < NWL; q++)
        pw[q] = *reinterpret_cast<const float4*>(W + (size_t)(n0 + lr + 64 * q) * K + lc * 4);

    for (int kt = 0; kt < K; kt += BK) {
        #pragma unroll
        for (int q = 0; q < NAL; q++) {
            As[lc * 4 + 0][lr + 64 * q] = pa[q].x;
            As[lc * 4 + 1][lr + 64 * q] = pa[q].y;
            As[lc * 4 + 2][lr + 64 * q] = pa[q].z;
            As[lc * 4 + 3][lr + 64 * q] = pa[q].w;
        }
        #pragma unroll
        for (int q = 0; q < NWL; q++) {
            Ws[lc * 4 + 0][lr + 64 * q] = pw[q].x;
            Ws[lc * 4 + 1][lr + 64 * q] = pw[q].y;
            Ws[lc * 4 + 2][lr + 64 * q] = pw[q].z;
            Ws[lc * 4 + 3][lr + 64 * q] = pw[q].w;
        }
        __syncthreads();

        if (kt + BK < K) {
            int kn = kt + BK;
            #pragma unroll
            for (int q = 0; q < NAL; q++) {
                int r = m0 + lr + 64 * q;
                pa[q] = (r < M) ? *reinterpret_cast<const float4*>(A + (size_t)r * K + kn + lc * 4) : f4z;
            }
            #pragma unroll
            for (int q = 0; q < NWL; q++)
                pw[q] = *reinterpret_cast<const float4*>(W + (size_t)(n0 + lr + 64 * q) * K + kn + lc * 4);
        }

        #pragma unroll
        for (int kk = 0; kk < BK; kk++) {
            float a[TM], w[TN];
            #pragma unroll
            for (int i4 = 0; i4 < TM; i4 += 4) {
                float4 v = *reinterpret_cast<const float4*>(&As[kk][ty * TM + i4]);
                a[i4 + 0] = v.x; a[i4 + 1] = v.y; a[i4 + 2] = v.z; a[i4 + 3] = v.w;
            }
            #pragma unroll
            for (int j4 = 0; j4 < TN; j4 += 4) {
                float4 v = *reinterpret_cast<const float4*>(&Ws[kk][tx * TN + j4]);
                w[j4 + 0] = v.x; w[j4 + 1] = v.y; w[j4 + 2] = v.z; w[j4 + 3] = v.w;
            }
            #pragma unroll
            for (int i = 0; i < TM; i++)
                #pragma unroll
                for (int j = 0; j < TN; j++)
                    acc[i][j] = fmaf(a[i], w[j], acc[i][j]);
        }
        __syncthreads();
    }

    #pragma unroll
    for (int i = 0; i < TM; i++) {
        int m = m0 + ty * TM + i;
        if (m >= M) continue;
        float* cr = C + (size_t)m * N + n0 + tx * TN;
        #pragma unroll
        for (int j4 = 0; j4 < TN; j4 += 4) {
            float4 v = make_float4(acc[i][j4], acc[i][j4 + 1], acc[i][j4 + 2], acc[i][j4 + 3]);
            if (ACCUM) {
                float4 o = *reinterpret_cast<const float4*>(cr + j4);
                v.x += o.x; v.y += o.y; v.z += o.z; v.w += o.w;
            }
            *reinterpret_cast<float4*>(cr + j4) = v;
        }
    }
}

// ---------------- fused conv+silu -> xproj -> dt (one block per token) ----------------
__global__ void __launch_bounds__(256)
mid_kernel(const float* __restrict__ cw, const float* __restrict__ cb,
           const float* __restrict__ xpw,
           const float* __restrict__ dtw, const float* __restrict__ dtb) {
    __shared__ float su[DI];
    __shared__ float sx[NXP];
    const int t = blockIdx.x;
    const int l = t % SEQ;
    const int tid = threadIdx.x;

    // conv + bias + SiLU
    #pragma unroll
    for (int d = tid; d < DI; d += 256) {
        float s = cb[d];
        #pragma unroll
        for (int k = 0; k < 4; k++) {
            int ls = l + k - 3;
            if (ls >= 0) s = fmaf(g_xz[(size_t)(t + k - 3) * (2 * DI) + d], cw[d * 4 + k], s);
        }
        float v = s / (1.f + __expf(-s));
        su[d] = v;
        g_u[(size_t)t * DI + d] = v;
    }
    __syncthreads();

    // xproj: 48 dots of length 512; warp w handles n = w*6..w*6+5
    {
        int wid = tid >> 5, lane = tid & 31;
        #pragma unroll
        for (int j = 0; j < 6; j++) {
            int n = wid * 6 + j;
            const float* wr = xpw + (size_t)n * DI;
            float s = 0.f;
            #pragma unroll
            for (int i = lane; i < DI; i += 32) s = fmaf(su[i], wr[i], s);
            #pragma unroll
            for (int o = 16; o > 0; o >>= 1) s += __shfl_xor_sync(0xffffffffu, s, o);
            if (lane == 0) {
                sx[n] = s;
                g_xdbc[(size_t)t * NXP + n] = s;
            }
        }
    }
    __syncthreads();

    // dt: softplus( sx[0:16] . dtw[d] + dtb[d] )
    #pragma unroll
    for (int d = tid; d < DI; d += 256) {
        const float* w = dtw + (size_t)d * DTR;
        float s = dtb[d];
        #pragma unroll
        for (int r = 0; r < DTR; r++) s = fmaf(sx[r], w[r], s);
        g_dt[(size_t)t * DI + d] = (s > 20.f) ? s : log1pf(__expf(s));
    }
}

// ---- chunked selective scan ----
// Pass 1: per chunk compute (prod dA, local scan end) with zero initial state.
__global__ void scan_pass1(const float* __restrict__ A_log) {
    int gid = blockIdx.x * 256 + threadIdx.x;   // 262144 threads
    int n = gid & 15;
    int r = gid >> 4;
    int d = r & (DI - 1);
    int b = (r >> 9) & (BATCH - 1);
    int c = r >> 10;
    const float Ac = -__expf(A_log[d * DS + n]);
    float state = 0.f, aprod = 1.f;
    const int t0 = b * SEQ + c * CLEN;
    #pragma unroll 5
    for (int l = 0; l < CLEN; l++) {
        int t = t0 + l;
        float dtv = g_dt[(size_t)t * DI + d];
        float uv  = g_u [(size_t)t * DI + d];
        float Bv  = g_xdbc[(size_t)t * NXP + DTR + n];
        float dA = __expf(dtv * Ac);
        aprod *= dA;
        state = fmaf(dA, state, dtv * Bv * uv);
    }
    int idx = ((c * BATCH + b) * DI + d) * DS + n;
    g_aprod[idx] = aprod;
    g_send[idx]  = state;
}

// Pass 2: recompute carry-in prefix inline (<=15 fma), rescan chunk, emit gated y.
__global__ void scan_pass2(const float* __restrict__ A_log,
                           const float* __restrict__ Dv) {
    int gid = blockIdx.x * 256 + threadIdx.x;   // 262144 threads
    int n = gid & 15;
    int r = gid >> 4;
    int d = r & (DI - 1);
    int b = (r >> 9) & (BATCH - 1);
    int c = r >> 10;
    const float Ac = -__expf(A_log[d * DS + n]);
    const float Dd = Dv[d];

    float state = 0.f;
    for (int cc = 0; cc < c; cc++) {
        int idx = ((cc * BATCH + b) * DI + d) * DS + n;
        state = fmaf(g_aprod[idx], state, g_send[idx]);
    }

    const int t0 = b * SEQ + c * CLEN;
    #pragma unroll 5
    for (int l = 0; l < CLEN; l++) {
        int t = t0 + l;
        float dtv = g_dt[(size_t)t * DI + d];
        float uv  = g_u [(size_t)t * DI + d];
        float Bv  = g_xdbc[(size_t)t * NXP + DTR + n];
        float Cv  = g_xdbc[(size_t)t * NXP + DTR + DS + n];
        float dA = __expf(dtv * Ac);
        state = fmaf(dA, state, dtv * Bv * uv);
        float p = state * Cv;
        p += __shfl_xor_sync(0xffffffffu, p, 1, 16);
        p += __shfl_xor_sync(0xffffffffu, p, 2, 16);
        p += __shfl_xor_sync(0xffffffffu, p, 4, 16);
        p += __shfl_xor_sync(0xffffffffu, p, 8, 16);
        if (n == 0) {
            float z = g_xz[(size_t)t * (2 * DI) + DI + d];
            g_y[(size_t)t * DI + d] = (p + uv * Dd) * (z / (1.f + __expf(-z)));
        }
    }
}

// Final LN + head dot product; one block per token
__global__ void final_kernel(const float* __restrict__ fw, const float* __restrict__ fb,
                             const float* __restrict__ hw, const float* __restrict__ hb,
                             float* __restrict__ out) {
    int t = blockIdx.x, d = threadIdx.x;
    float v = g_h[t * DM + d];
    float mean = blockReduceSum256(v) * (1.f / DM);
    float diff = v - mean;
    float var = blockReduceSum256(diff * diff) * (1.f / DM);
    float nr = diff * rsqrtf(var + 1e-5f) * fw[d] + fb[d];
    float s = blockReduceSum256(nr * hw[d]);
    if (d == 0) out[t] = s + hb[0];
}

// ---------------- launch ----------------
extern "C" void kernel_launch(void* const* d_in, const int* in_sizes, int n_in,
                              void* d_out, int out_size) {
    const float* x         = (const float*)d_in[0];
    const float* bulk_in_w = (const float*)d_in[1];
    const float* bulk_in_b = (const float*)d_in[2];
    const float* gene_emb  = (const float*)d_in[3];
    const float* mod_emb   = (const float*)d_in[4];
    const float* ln_w      = (const float*)d_in[5];
    const float* ln_b      = (const float*)d_in[6];
    const float* in_proj_w = (const float*)d_in[7];
    const float* conv_w    = (const float*)d_in[8];
    const float* conv_b    = (const float*)d_in[9];
    const float* x_proj_w  = (const float*)d_in[10];
    const float* dt_proj_w = (const float*)d_in[11];
    const float* dt_proj_b = (const float*)d_in[12];
    const float* A_log     = (const float*)d_in[13];
    const float* Dvec      = (const float*)d_in[14];
    const float* out_proj_w= (const float*)d_in[15];
    const float* fin_w     = (const float*)d_in[16];
    const float* fin_b     = (const float*)d_in[17];
    const float* head_w    = (const float*)d_in[18];
    const float* head_b    = (const float*)d_in[19];
    float* out = (float*)d_out;

    float *p_h, *p_hn, *p_xz, *p_y;
    cudaGetSymbolAddress((void**)&p_h,  g_h);
    cudaGetSymbolAddress((void**)&p_hn, g_hn);
    cudaGetSymbolAddress((void**)&p_xz, g_xz);
    cudaGetSymbolAddress((void**)&p_y,  g_y);

    embed_kernel<<<(NT * DM + 255) / 256, 256>>>(x, bulk_in_w, bulk_in_b, gene_emb, mod_emb);

    for (int i = 0; i < NL; i++) {
        ln_kernel<<<NT, 256>>>(p_h, p_hn, ln_w + i * DM, ln_b + i * DM);

        // xz = hn @ in_proj_w^T   (M=4000, N=1024, K=256)  [128x64 tiles]
        sgemm_nt2<128, 64, 0><<<dim3((2 * DI) / 64, (NT + 127) / 128), 256>>>(
            p_hn, in_proj_w + (size_t)i * (2 * DI) * DM, p_xz, NT, 2 * DI, DM);

        mid_kernel<<<NT, 256>>>(conv_w + (size_t)i * DI * 4, conv_b + (size_t)i * DI,
                                x_proj_w + (size_t)i * NXP * DI,
                                dt_proj_w + (size_t)i * DI * DTR, dt_proj_b + (size_t)i * DI);

        scan_pass1<<<(BATCH * DI * DS * NCHUNK) / 256, 256>>>(A_log + (size_t)i * DI * DS);
        scan_pass2<<<(BATCH * DI * DS * NCHUNK) / 256, 256>>>(A_log + (size_t)i * DI * DS,
                                                              Dvec + (size_t)i * DI);

        // h += y @ out_proj_w^T   (M=4000, N=256, K=512)  [64x64 tiles]
        sgemm_nt2<64, 64, 1><<<dim3(DM / 64, (NT + 63) / 64), 256>>>(
            p_y, out_proj_w + (size_t)i * DM * DI, p_h, NT, DM, DI);
    }

    final_kernel<<<NT, 256>>>(fin_w, fin_b, head_w, head_b, out);
}